// round 4
// baseline (speedup 1.0000x reference)
#include <cuda_runtime.h>
#include <math.h>

// Problem constants
#define CIN   64
#define COUT  128
#define HH    128
#define WW    128
#define NB    32
#define TPB   256
#define IC_CHUNK 8
#define NCHUNK (CIN / IC_CHUNK)

// smem: x tile [64 ic][3 rows][128 cols] + weight chunk [8*9][128 oc]
#define XS_FLOATS (CIN * 3 * WW)            // 24576
#define WS_FLOATS (IC_CHUNK * 9 * COUT)     // 9216
#define SMEM_BYTES ((XS_FLOATS + WS_FLOATS) * 4)   // 135168

__device__ __forceinline__ float gelu_tanh(float y) {
    float u = 0.7978845608f * (y + 0.044715f * y * y * y);
    return 0.5f * y * (1.0f + tanhf(u));
}

__device__ __forceinline__ unsigned long long pack2(float a) {
    unsigned long long r;
    asm("mov.b64 %0, {%1, %1};" : "=l"(r) : "f"(a));
    return r;
}

__device__ __forceinline__ void fma2(unsigned long long& d,
                                     unsigned long long a,
                                     unsigned long long b) {
    asm("fma.rn.f32x2 %0, %1, %2, %0;" : "+l"(d) : "l"(a), "l"(b));
}

extern __shared__ float smem[];

__global__ __launch_bounds__(TPB, 1)
void fused_convt_gelu_gn_kernel(const float* __restrict__ x,
                                const float* __restrict__ w,
                                const float* __restrict__ bias,
                                const float* __restrict__ gnw,
                                const float* __restrict__ gnb,
                                float* __restrict__ out) {
    float* xs = smem;                 // [ic*3 + r][col]
    float* ws = smem + XS_FLOATS;     // [(icl*3+kh)*3+kw][oc]

    const int h = blockIdx.x;
    const int n = blockIdx.y;
    const int t = threadIdx.x;
    const int ocg = t >> 4;           // 0..15  -> oc base = ocg*8
    const int cg  = t & 15;           // 0..15  -> col base = cg*8
    const int o0 = ocg * 8;
    const int c0 = cg * 8;

    // ---- load x tile: global rows h-2+r, zero-padded at top boundary ----
    {
        const float* xb = x + (size_t)n * CIN * HH * WW;
        // 192 rows * 32 float4 = 6144 float4
        for (int i = t; i < (CIN * 3 * WW) / 4; i += TPB) {
            int col4 = i & 31;
            int row  = i >> 5;                 // ic*3 + r
            int ic = row / 3, r = row - ic * 3;
            int gh = h - 2 + r;
            float4 v = make_float4(0.f, 0.f, 0.f, 0.f);
            if (gh >= 0)
                v = *(const float4*)(xb + ((size_t)ic * HH + gh) * WW + col4 * 4);
            *(float4*)(xs + row * WW + col4 * 4) = v;
        }
    }

    // ---- accumulators: 8 cols x 4 oc-pairs of f32x2 ----
    unsigned long long acc[8][4];
#pragma unroll
    for (int j = 0; j < 8; j++)
#pragma unroll
        for (int p = 0; p < 4; p++) acc[j][p] = 0ULL;

#pragma unroll 1
    for (int ch = 0; ch < NCHUNK; ch++) {
        __syncthreads();   // prev-chunk readers done before ws overwrite
        {
            const int ic0 = ch * IC_CHUNK;
#pragma unroll
            for (int i = 0; i < 4; i++) {
                int f = t + i * TPB;           // 0..1023 = icl*128 + oc
                int icl = f >> 7, oc = f & 127;
                const float* wg = w + ((size_t)(ic0 + icl) * COUT + oc) * 9;
#pragma unroll
                for (int q = 0; q < 9; q++)
                    ws[(icl * 9 + q) * COUT + oc] = wg[q];
            }
        }
        __syncthreads();

#pragma unroll 1
        for (int icl = 0; icl < IC_CHUNK; icl++) {
            const float* xrowbase = xs + (size_t)((ch * IC_CHUNK + icl) * 3) * WW;
#pragma unroll
            for (int r = 0; r < 3; r++) {
                const float* xr = xrowbase + r * WW + c0;
                float xv[10];                      // xv[i] = x[c0-2+i]
                if (cg) {
                    float4 a = *(const float4*)(xr - 4);
                    xv[0] = a.z; xv[1] = a.w;
                } else {
                    xv[0] = 0.f; xv[1] = 0.f;
                }
                float4 bq = *(const float4*)(xr);
                xv[2] = bq.x; xv[3] = bq.y; xv[4] = bq.z; xv[5] = bq.w;
                float4 cq = *(const float4*)(xr + 4);
                xv[6] = cq.x; xv[7] = cq.y; xv[8] = cq.z; xv[9] = cq.w;

                unsigned long long xp[10];
#pragma unroll
                for (int i = 0; i < 10; i++) xp[i] = pack2(xv[i]);

                const int kh = 2 - r;
#pragma unroll
                for (int kw = 0; kw < 3; kw++) {
                    const unsigned long long* wr = (const unsigned long long*)
                        (ws + ((icl * 3 + kh) * 3 + kw) * COUT + o0);
                    unsigned long long wp[4];
#pragma unroll
                    for (int p = 0; p < 4; p++) wp[p] = wr[p];
#pragma unroll
                    for (int j = 0; j < 8; j++) {
                        unsigned long long xx = xp[j + 2 - kw];
#pragma unroll
                        for (int p = 0; p < 4; p++) fma2(acc[j][p], xx, wp[p]);
                    }
                }
            }
        }
    }

    // ---- epilogue: bias + tanh-GELU ----
    float bb[8], gwv[8], gbv[8];
#pragma unroll
    for (int p = 0; p < 8; p++) {
        bb[p]  = __ldg(bias + o0 + p);
        gwv[p] = __ldg(gnw  + o0 + p);
        gbv[p] = __ldg(gnb  + o0 + p);
    }

    float g[8][8];  // [col j][oc local]
#pragma unroll
    for (int j = 0; j < 8; j++) {
#pragma unroll
        for (int p = 0; p < 4; p++) {
            float lo, hi;
            asm("mov.b64 {%0, %1}, %2;" : "=f"(lo), "=f"(hi) : "l"(acc[j][p]));
            g[j][2 * p]     = gelu_tanh(lo + bb[2 * p]);
            g[j][2 * p + 1] = gelu_tanh(hi + bb[2 * p + 1]);
        }
    }

    // ---- per-pixel group stats (group = 16 oc = this thread + partner t^16) ----
    float mean[8], rstd[8];
#pragma unroll
    for (int j = 0; j < 8; j++) {
        float s1 = 0.f, s2 = 0.f;
#pragma unroll
        for (int p = 0; p < 8; p++) { s1 += g[j][p]; s2 += g[j][p] * g[j][p]; }
        s1 += __shfl_xor_sync(0xffffffffu, s1, 16);
        s2 += __shfl_xor_sync(0xffffffffu, s2, 16);
        float m = s1 * (1.0f / 16.0f);
        float v = s2 * (1.0f / 16.0f) - m * m;
        mean[j] = m;
        rstd[j] = rsqrtf(v + 1e-5f);
    }

    // ---- normalize + affine + coalesced float4 stores ----
#pragma unroll
    for (int p = 0; p < 8; p++) {
        float o[8];
#pragma unroll
        for (int j = 0; j < 8; j++)
            o[j] = (g[j][p] - mean[j]) * rstd[j] * gwv[p] + gbv[p];
        float* dst = out + (((size_t)n * COUT + (o0 + p)) * HH + h) * WW + c0;
        *(float4*)(dst)     = make_float4(o[0], o[1], o[2], o[3]);
        *(float4*)(dst + 4) = make_float4(o[4], o[5], o[6], o[7]);
    }
}

extern "C" void kernel_launch(void* const* d_in, const int* in_sizes, int n_in,
                              void* d_out, int out_size) {
    const float* x   = (const float*)d_in[0];
    const float* w   = (const float*)d_in[1];
    const float* b   = (const float*)d_in[2];
    const float* gnw = (const float*)d_in[3];
    const float* gnb = (const float*)d_in[4];
    float* out = (float*)d_out;

    cudaFuncSetAttribute(fused_convt_gelu_gn_kernel,
                         cudaFuncAttributeMaxDynamicSharedMemorySize, SMEM_BYTES);
    dim3 grid(HH, NB);
    fused_convt_gelu_gn_kernel<<<grid, TPB, SMEM_BYTES>>>(x, w, b, gnw, gnb, out);
}

// round 5
// speedup vs baseline: 1.1572x; 1.1572x over previous
#include <cuda_runtime.h>
#include <math.h>

// Problem constants
#define CIN   64
#define COUT  128
#define HH    128
#define WW    128
#define NB    32
#define TPB   256
#define IC_CHUNK 8
#define NCHUNK (CIN / IC_CHUNK)

// smem per CTA: x chunk [8 ic][3 rows][128 cols] + weight chunk [8*9][128 oc]
#define XS_FLOATS (IC_CHUNK * 3 * WW)       // 3072  (12 KB)
#define WS_FLOATS (IC_CHUNK * 9 * COUT)     // 9216  (36 KB)
#define SMEM_BYTES ((XS_FLOATS + WS_FLOATS) * 4)   // 49152 -> 2 CTAs/SM

__device__ __forceinline__ float gelu_tanh(float y) {
    float u = 0.7978845608f * (y + 0.044715f * y * y * y);
    return 0.5f * y * (1.0f + tanhf(u));
}

__device__ __forceinline__ unsigned long long pack2(float a) {
    unsigned long long r;
    asm("mov.b64 %0, {%1, %1};" : "=l"(r) : "f"(a));
    return r;
}

__device__ __forceinline__ void fma2(unsigned long long& d,
                                     unsigned long long a,
                                     unsigned long long b) {
    asm("fma.rn.f32x2 %0, %1, %2, %0;" : "+l"(d) : "l"(a), "l"(b));
}

extern __shared__ float smem[];

__global__ __launch_bounds__(TPB, 2)
void fused_convt_gelu_gn_kernel(const float* __restrict__ x,
                                const float* __restrict__ w,
                                const float* __restrict__ bias,
                                const float* __restrict__ gnw,
                                const float* __restrict__ gnb,
                                float* __restrict__ out) {
    float* xs = smem;                 // [icl*3 + r][col]
    float* ws = smem + XS_FLOATS;     // [(icl*3+kh)*3+kw][oc]

    const int h = blockIdx.x;
    const int n = blockIdx.y;
    const int t = threadIdx.x;
    const int ocg = t >> 4;           // 0..15  -> oc base = ocg*8
    const int cg  = t & 15;           // 0..15  -> col base = cg*8
    const int o0 = ocg * 8;
    const int c0 = cg * 8;

    // ---- accumulators: 8 cols x 4 oc-pairs of f32x2 ----
    unsigned long long acc[8][4];
#pragma unroll
    for (int j = 0; j < 8; j++)
#pragma unroll
        for (int p = 0; p < 4; p++) acc[j][p] = 0ULL;

    const float* xb = x + (size_t)n * CIN * HH * WW;

#pragma unroll 1
    for (int ch = 0; ch < NCHUNK; ch++) {
        const int ic0 = ch * IC_CHUNK;
        __syncthreads();   // prev-chunk readers done before smem overwrite

        // ---- load x chunk: 8 ic x 3 rows x 128 cols = 768 float4 ----
#pragma unroll
        for (int i = 0; i < 3; i++) {
            int f = t + i * TPB;               // 0..767
            int col4 = f & 31;
            int row  = f >> 5;                 // icl*3 + r  (0..23)
            int icl = row / 3, r = row - icl * 3;
            int gh = h - 2 + r;
            float4 v = make_float4(0.f, 0.f, 0.f, 0.f);
            if (gh >= 0)
                v = *(const float4*)(xb + ((size_t)(ic0 + icl) * HH + gh) * WW + col4 * 4);
            *(float4*)(xs + row * WW + col4 * 4) = v;
        }

        // ---- load w chunk: 8 ic x 128 oc x 9 taps ----
#pragma unroll
        for (int i = 0; i < 4; i++) {
            int f = t + i * TPB;               // 0..1023 = icl*128 + oc
            int icl = f >> 7, oc = f & 127;
            const float* wg = w + ((size_t)(ic0 + icl) * COUT + oc) * 9;
#pragma unroll
            for (int q = 0; q < 9; q++)
                ws[(icl * 9 + q) * COUT + oc] = wg[q];
        }
        __syncthreads();

        // ---- compute ----
#pragma unroll 1
        for (int icl = 0; icl < IC_CHUNK; icl++) {
            const float* xrowbase = xs + (size_t)(icl * 3) * WW;
#pragma unroll
            for (int r = 0; r < 3; r++) {
                const float* xr = xrowbase + r * WW + c0;
                float xv[10];                      // xv[i] = x[c0-2+i]
                if (cg) {
                    float4 a = *(const float4*)(xr - 4);
                    xv[0] = a.z; xv[1] = a.w;
                } else {
                    xv[0] = 0.f; xv[1] = 0.f;
                }
                float4 bq = *(const float4*)(xr);
                xv[2] = bq.x; xv[3] = bq.y; xv[4] = bq.z; xv[5] = bq.w;
                float4 cq = *(const float4*)(xr + 4);
                xv[6] = cq.x; xv[7] = cq.y; xv[8] = cq.z; xv[9] = cq.w;

                unsigned long long xp[10];
#pragma unroll
                for (int i = 0; i < 10; i++) xp[i] = pack2(xv[i]);

                const int kh = 2 - r;
#pragma unroll
                for (int kw = 0; kw < 3; kw++) {
                    const unsigned long long* wr = (const unsigned long long*)
                        (ws + ((icl * 3 + kh) * 3 + kw) * COUT + o0);
                    unsigned long long wp[4];
#pragma unroll
                    for (int p = 0; p < 4; p++) wp[p] = wr[p];
#pragma unroll
                    for (int j = 0; j < 8; j++) {
                        unsigned long long xx = xp[j + 2 - kw];
#pragma unroll
                        for (int p = 0; p < 4; p++) fma2(acc[j][p], xx, wp[p]);
                    }
                }
            }
        }
    }

    // ---- epilogue: bias + tanh-GELU ----
    float bb[8], gwv[8], gbv[8];
#pragma unroll
    for (int p = 0; p < 8; p++) {
        bb[p]  = __ldg(bias + o0 + p);
        gwv[p] = __ldg(gnw  + o0 + p);
        gbv[p] = __ldg(gnb  + o0 + p);
    }

    float g[8][8];  // [col j][oc local]
#pragma unroll
    for (int j = 0; j < 8; j++) {
#pragma unroll
        for (int p = 0; p < 4; p++) {
            float lo, hi;
            asm("mov.b64 {%0, %1}, %2;" : "=f"(lo), "=f"(hi) : "l"(acc[j][p]));
            g[j][2 * p]     = gelu_tanh(lo + bb[2 * p]);
            g[j][2 * p + 1] = gelu_tanh(hi + bb[2 * p + 1]);
        }
    }

    // ---- per-pixel group stats (group = 16 oc = this thread + partner t^16) ----
    float mean[8], rstd[8];
#pragma unroll
    for (int j = 0; j < 8; j++) {
        float s1 = 0.f, s2 = 0.f;
#pragma unroll
        for (int p = 0; p < 8; p++) { s1 += g[j][p]; s2 += g[j][p] * g[j][p]; }
        s1 += __shfl_xor_sync(0xffffffffu, s1, 16);
        s2 += __shfl_xor_sync(0xffffffffu, s2, 16);
        float m = s1 * (1.0f / 16.0f);
        float v = s2 * (1.0f / 16.0f) - m * m;
        mean[j] = m;
        rstd[j] = rsqrtf(v + 1e-5f);
    }

    // ---- normalize + affine + coalesced float4 stores ----
#pragma unroll
    for (int p = 0; p < 8; p++) {
        float o[8];
#pragma unroll
        for (int j = 0; j < 8; j++)
            o[j] = (g[j][p] - mean[j]) * rstd[j] * gwv[p] + gbv[p];
        float* dst = out + (((size_t)n * COUT + (o0 + p)) * HH + h) * WW + c0;
        *(float4*)(dst)     = make_float4(o[0], o[1], o[2], o[3]);
        *(float4*)(dst + 4) = make_float4(o[4], o[5], o[6], o[7]);
    }
}

extern "C" void kernel_launch(void* const* d_in, const int* in_sizes, int n_in,
                              void* d_out, int out_size) {
    const float* x   = (const float*)d_in[0];
    const float* w   = (const float*)d_in[1];
    const float* b   = (const float*)d_in[2];
    const float* gnw = (const float*)d_in[3];
    const float* gnb = (const float*)d_in[4];
    float* out = (float*)d_out;

    cudaFuncSetAttribute(fused_convt_gelu_gn_kernel,
                         cudaFuncAttributeMaxDynamicSharedMemorySize, SMEM_BYTES);
    dim3 grid(HH, NB);
    fused_convt_gelu_gn_kernel<<<grid, TPB, SMEM_BYTES>>>(x, w, b, gnw, gnb, out);
}

// round 6
// speedup vs baseline: 1.2169x; 1.0516x over previous
#include <cuda_runtime.h>
#include <math.h>

// Problem constants
#define CIN   64
#define COUT  128
#define HH    128
#define WW    128
#define NB    32
#define TPB   256
#define IC_CHUNK 8
#define NCHUNK (CIN / IC_CHUNK)

// Per pipeline stage: x chunk [8 ic][3 rows][128 cols] + w chunk [8*9][128 oc]
#define XS_FLOATS (IC_CHUNK * 3 * WW)       // 3072  (12 KB)
#define WS_FLOATS (IC_CHUNK * 9 * COUT)     // 9216  (36 KB)
#define STAGE_FLOATS (XS_FLOATS + WS_FLOATS)        // 12288 (48 KB)
#define SMEM_BYTES (2 * STAGE_FLOATS * 4)           // 98304 -> 2 CTAs/SM

// Pre-transposed weights: wT[(ic*9 + q)*COUT + oc]
__device__ float g_wT[CIN * 9 * COUT];

__global__ void transpose_w_kernel(const float* __restrict__ w) {
    int idx = blockIdx.x * blockDim.x + threadIdx.x;   // 0..73727
    if (idx >= CIN * COUT * 9) return;
    int ic = idx / (COUT * 9);
    int rem = idx - ic * (COUT * 9);
    int oc = rem / 9;
    int q  = rem - oc * 9;
    g_wT[(ic * 9 + q) * COUT + oc] = w[idx];
}

__device__ __forceinline__ float gelu_tanh(float y) {
    float u = 0.7978845608f * (y + 0.044715f * y * y * y);
    return 0.5f * y * (1.0f + tanhf(u));
}

__device__ __forceinline__ unsigned long long pack2(float a) {
    unsigned long long r;
    asm("mov.b64 %0, {%1, %1};" : "=l"(r) : "f"(a));
    return r;
}

__device__ __forceinline__ void fma2(unsigned long long& d,
                                     unsigned long long a,
                                     unsigned long long b) {
    asm("fma.rn.f32x2 %0, %1, %2, %0;" : "+l"(d) : "l"(a), "l"(b));
}

__device__ __forceinline__ void cp16(float* dst_smem, const float* src_gmem,
                                     int src_bytes) {
    unsigned sdst = (unsigned)__cvta_generic_to_shared(dst_smem);
    asm volatile("cp.async.cg.shared.global [%0], [%1], 16, %2;"
                 :: "r"(sdst), "l"(src_gmem), "r"(src_bytes));
}

extern __shared__ float smem[];

__global__ __launch_bounds__(TPB, 2)
void fused_convt_gelu_gn_kernel(const float* __restrict__ x,
                                const float* __restrict__ bias,
                                const float* __restrict__ gnw,
                                const float* __restrict__ gnb,
                                float* __restrict__ out) {
    const int h = blockIdx.x;
    const int n = blockIdx.y;
    const int t = threadIdx.x;
    const int ocg = t >> 4;           // 0..15  -> oc base = ocg*8
    const int cg  = t & 15;           // 0..15  -> col base = cg*8
    const int o0 = ocg * 8;
    const int c0 = cg * 8;

    const float* xb = x + (size_t)n * CIN * HH * WW;

    // ---- prefetch helper (x: 3x16B, w: 9x16B per thread, all cp.async) ----
    auto prefetch = [&](int ch, int stage) {
        float* xs = smem + stage * STAGE_FLOATS;
        float* ws = xs + XS_FLOATS;
        const int ic0 = ch * IC_CHUNK;
        // x chunk: 768 float4
#pragma unroll
        for (int i = 0; i < 3; i++) {
            int f = t + i * TPB;               // 0..767
            int col4 = f & 31;
            int row  = f >> 5;                 // icl*3 + r  (0..23)
            int icl = row / 3, r = row - icl * 3;
            int gh = h - 2 + r;
            const float* src = (gh >= 0)
                ? xb + ((size_t)(ic0 + icl) * HH + gh) * WW + col4 * 4
                : xb;                           // valid addr, 0 bytes read
            cp16(xs + row * WW + col4 * 4, src, (gh >= 0) ? 16 : 0);
        }
        // w chunk: contiguous 9216 floats in g_wT, 2304 float4
        const float* wsrc = g_wT + (size_t)ic0 * 9 * COUT;
#pragma unroll
        for (int i = 0; i < 9; i++) {
            int f4 = t + i * TPB;              // 0..2303
            cp16(ws + f4 * 4, wsrc + f4 * 4, 16);
        }
        asm volatile("cp.async.commit_group;");
    };

    // ---- accumulators: 8 cols x 4 oc-pairs of f32x2 ----
    unsigned long long acc[8][4];
#pragma unroll
    for (int j = 0; j < 8; j++)
#pragma unroll
        for (int p = 0; p < 4; p++) acc[j][p] = 0ULL;

    prefetch(0, 0);

#pragma unroll 1
    for (int ch = 0; ch < NCHUNK; ch++) {
        asm volatile("cp.async.wait_group 0;");
        __syncthreads();   // stage ch%2 filled; everyone done reading stage (ch+1)%2

        if (ch + 1 < NCHUNK) prefetch(ch + 1, (ch + 1) & 1);

        const float* stage = smem + (ch & 1) * STAGE_FLOATS;
        const float* xsS = stage;
        const float* wsS = stage + XS_FLOATS;

        // ---- compute ----
#pragma unroll 1
        for (int icl = 0; icl < IC_CHUNK; icl++) {
            const float* xrowbase = xsS + (size_t)(icl * 3) * WW;
#pragma unroll
            for (int r = 0; r < 3; r++) {
                const float* xr = xrowbase + r * WW + c0;
                float xv[10];                      // xv[i] = x[c0-2+i]
                if (cg) {
                    float4 a = *(const float4*)(xr - 4);
                    xv[0] = a.z; xv[1] = a.w;
                } else {
                    xv[0] = 0.f; xv[1] = 0.f;
                }
                float4 bq = *(const float4*)(xr);
                xv[2] = bq.x; xv[3] = bq.y; xv[4] = bq.z; xv[5] = bq.w;
                float4 cq = *(const float4*)(xr + 4);
                xv[6] = cq.x; xv[7] = cq.y; xv[8] = cq.z; xv[9] = cq.w;

                unsigned long long xp[10];
#pragma unroll
                for (int i = 0; i < 10; i++) xp[i] = pack2(xv[i]);

                const int kh = 2 - r;
#pragma unroll
                for (int kw = 0; kw < 3; kw++) {
                    const unsigned long long* wr = (const unsigned long long*)
                        (wsS + ((icl * 3 + kh) * 3 + kw) * COUT + o0);
                    unsigned long long wp[4];
#pragma unroll
                    for (int p = 0; p < 4; p++) wp[p] = wr[p];
#pragma unroll
                    for (int j = 0; j < 8; j++) {
                        unsigned long long xx = xp[j + 2 - kw];
#pragma unroll
                        for (int p = 0; p < 4; p++) fma2(acc[j][p], xx, wp[p]);
                    }
                }
            }
        }
    }

    // ---- epilogue: bias + tanh-GELU ----
    float bb[8], gwv[8], gbv[8];
#pragma unroll
    for (int p = 0; p < 8; p++) {
        bb[p]  = __ldg(bias + o0 + p);
        gwv[p] = __ldg(gnw  + o0 + p);
        gbv[p] = __ldg(gnb  + o0 + p);
    }

    float g[8][8];  // [col j][oc local]
#pragma unroll
    for (int j = 0; j < 8; j++) {
#pragma unroll
        for (int p = 0; p < 4; p++) {
            float lo, hi;
            asm("mov.b64 {%0, %1}, %2;" : "=f"(lo), "=f"(hi) : "l"(acc[j][p]));
            g[j][2 * p]     = gelu_tanh(lo + bb[2 * p]);
            g[j][2 * p + 1] = gelu_tanh(hi + bb[2 * p + 1]);
        }
    }

    // ---- per-pixel group stats (group = 16 oc = this thread + partner t^16) ----
    float mean[8], rstd[8];
#pragma unroll
    for (int j = 0; j < 8; j++) {
        float s1 = 0.f, s2 = 0.f;
#pragma unroll
        for (int p = 0; p < 8; p++) { s1 += g[j][p]; s2 += g[j][p] * g[j][p]; }
        s1 += __shfl_xor_sync(0xffffffffu, s1, 16);
        s2 += __shfl_xor_sync(0xffffffffu, s2, 16);
        float m = s1 * (1.0f / 16.0f);
        float v = s2 * (1.0f / 16.0f) - m * m;
        mean[j] = m;
        rstd[j] = rsqrtf(v + 1e-5f);
    }

    // ---- normalize + affine + coalesced float4 stores ----
#pragma unroll
    for (int p = 0; p < 8; p++) {
        float o[8];
#pragma unroll
        for (int j = 0; j < 8; j++)
            o[j] = (g[j][p] - mean[j]) * rstd[j] * gwv[p] + gbv[p];
        float* dst = out + (((size_t)n * COUT + (o0 + p)) * HH + h) * WW + c0;
        *(float4*)(dst)     = make_float4(o[0], o[1], o[2], o[3]);
        *(float4*)(dst + 4) = make_float4(o[4], o[5], o[6], o[7]);
    }
}

extern "C" void kernel_launch(void* const* d_in, const int* in_sizes, int n_in,
                              void* d_out, int out_size) {
    const float* x   = (const float*)d_in[0];
    const float* w   = (const float*)d_in[1];
    const float* b   = (const float*)d_in[2];
    const float* gnw = (const float*)d_in[3];
    const float* gnb = (const float*)d_in[4];
    float* out = (float*)d_out;

    transpose_w_kernel<<<(CIN * COUT * 9 + 255) / 256, 256>>>(w);

    cudaFuncSetAttribute(fused_convt_gelu_gn_kernel,
                         cudaFuncAttributeMaxDynamicSharedMemorySize, SMEM_BYTES);
    dim3 grid(HH, NB);
    fused_convt_gelu_gn_kernel<<<grid, TPB, SMEM_BYTES>>>(x, b, gnw, gnb, out);
}

// round 8
// speedup vs baseline: 1.6007x; 1.3154x over previous
#include <cuda_runtime.h>
#include <cuda_bf16.h>
#include <math.h>
#include <stdint.h>

#define CIN   64
#define COUT  128
#define HH    128
#define WW    128
#define NB    32

// ---------------- persistent scratch (__device__ globals) -------------------
// Weights: [tap][split][oc(128)][ic(64)] bf16, 128B rows  (16KB per tile)
__device__ uint4 g_w2[9 * 2 * 1024];
// Activations: [n][h][split][pix(128)][ic(64)] bf16, 128B rows
__device__ uint4 g_x2[(size_t)NB * HH * 2 * 1024];

// ---------------- pre-pass: weights -> split + transposed tiles -------------
__global__ void prep_w(const float* __restrict__ w) {
    __shared__ __nv_bfloat16 sh[2][8192];
    const int tap = blockIdx.x;             // kh*3+kw
    const int kh = tap / 3, kw = tap % 3;
    for (int f = threadIdx.x; f < 8192; f += 256) {   // f = oc*64 + ic
        int oc = f >> 6, ic = f & 63;
        float v = w[((size_t)(ic * COUT + oc) * 3 + kh) * 3 + kw];
        __nv_bfloat16 hi = __float2bfloat16(v);
        __nv_bfloat16 lo = __float2bfloat16(v - __bfloat162float(hi));
        sh[0][f] = hi;
        sh[1][f] = lo;
    }
    __syncthreads();
    for (int f = threadIdx.x; f < 2048; f += 256) {
        int s = f >> 10, q = f & 1023;
        g_w2[(tap * 2 + s) * 1024 + q] = ((const uint4*)sh[s])[q];
    }
}

// ---------------- pre-pass: x -> split + transposed tiles -------------------
__global__ void prep_x(const float* __restrict__ x) {
    __shared__ __nv_bfloat16 sh[2][8192];
    const int h = blockIdx.x, n = blockIdx.y;
    const float* xb = x + (size_t)n * CIN * HH * WW;
#pragma unroll
    for (int i = 0; i < 8; i++) {
        int f = threadIdx.x + i * 256;      // 0..2047 = ic*32 + p4
        int ic = f >> 5, p4 = f & 31;
        float4 v = *(const float4*)(xb + ((size_t)ic * HH + h) * WW + p4 * 4);
        float vv[4] = {v.x, v.y, v.z, v.w};
#pragma unroll
        for (int j = 0; j < 4; j++) {
            int p = p4 * 4 + j;
            __nv_bfloat16 hi = __float2bfloat16(vv[j]);
            __nv_bfloat16 lo = __float2bfloat16(vv[j] - __bfloat162float(hi));
            sh[0][p * 64 + ic] = hi;
            sh[1][p * 64 + ic] = lo;
        }
    }
    __syncthreads();
    size_t base = ((size_t)(n * HH + h) * 2) * 1024;
    for (int f = threadIdx.x; f < 2048; f += 256) {
        int s = f >> 10, q = f & 1023;
        g_x2[base + (size_t)s * 1024 + q] = ((const uint4*)sh[s])[q];
    }
}

// ---------------- main kernel ----------------------------------------------
// smem rows padded to 144B (9x16B) -> conflict-free ldmatrix.
#define XROW   144
#define XT_B   (128 * XROW)            // 18432 per tile
#define SM_ZERO 0                       // 256B of zeros
#define SM_X   256                      // 6 X tiles (kh x split)
#define SM_W   (256 + 6 * XT_B)         // 110848; 2 W bufs (tap double buffer)
#define WBUF_B (2 * XT_B)               // 36864
#define SMEM_SZ (SM_W + 2 * WBUF_B)     // 184576

static __device__ __forceinline__ unsigned smem_u32(const void* p) {
    unsigned r;
    asm("{ .reg .u64 t; cvta.to.shared.u64 t, %1; cvt.u32.u64 %0, t; }"
        : "=r"(r) : "l"(p));
    return r;
}

__device__ __forceinline__ void cp16(unsigned dst, const void* src, int bytes) {
    asm volatile("cp.async.cg.shared.global [%0], [%1], 16, %2;"
                 :: "r"(dst), "l"(src), "r"(bytes));
}
__device__ __forceinline__ void cp_commit() {
    asm volatile("cp.async.commit_group;");
}

__device__ __forceinline__ void ldsm4(unsigned r[4], unsigned addr) {
    asm volatile("ldmatrix.sync.aligned.m8n8.x4.shared.b16 {%0,%1,%2,%3}, [%4];"
                 : "=r"(r[0]), "=r"(r[1]), "=r"(r[2]), "=r"(r[3]) : "r"(addr));
}

__device__ __forceinline__ void mma16816(float c[4], const unsigned a[4],
                                         unsigned b0, unsigned b1) {
    asm volatile(
        "mma.sync.aligned.m16n8k16.row.col.f32.bf16.bf16.f32 "
        "{%0,%1,%2,%3}, {%4,%5,%6,%7}, {%8,%9}, {%0,%1,%2,%3};"
        : "+f"(c[0]), "+f"(c[1]), "+f"(c[2]), "+f"(c[3])
        : "r"(a[0]), "r"(a[1]), "r"(a[2]), "r"(a[3]), "r"(b0), "r"(b1));
}

__device__ __forceinline__ float gelu_tanh(float y) {
    float u = 0.7978845608f * (y + 0.044715f * y * y * y);
    return 0.5f * y * (1.0f + tanhf(u));
}

extern __shared__ char dyn_smem[];

__global__ __launch_bounds__(256, 1)
void convt_hmma_kernel(const float* __restrict__ bias,
                       const float* __restrict__ gnw,
                       const float* __restrict__ gnb,
                       float* __restrict__ out) {
    const int h = blockIdx.x;
    const int n = blockIdx.y;
    const int tid = threadIdx.x;
    const int wid = tid >> 5;
    const int l = tid & 31;
    const int wm = wid >> 1;          // 0..3 -> oc base wm*32
    const int wn = wid & 1;           // 0..1 -> pixel base wn*64

    const unsigned sb = smem_u32(dyn_smem);

    // zero region for out-of-range B rows
    if (tid < 64) *(float*)(dyn_smem + tid * 4) = 0.f;

    // ---- prologue: X tiles (6 x 1024 chunks) ----
#pragma unroll
    for (int i = 0; i < 24; i++) {
        int idx = tid + i * 256;           // 0..6143
        int tile = idx >> 10, q = idx & 1023;
        int kh = tile >> 1, s = tile & 1;
        int gh = h - kh;
        int row = q >> 3, c = q & 7;
        const uint4* src = g_x2 +
            ((size_t)(n * HH + (gh < 0 ? 0 : gh)) * 2 + s) * 1024 + q;
        cp16(sb + SM_X + tile * XT_B + row * XROW + c * 16, src,
             (gh >= 0) ? 16 : 0);
    }
    cp_commit();

    auto load_w = [&](int tap, int buf) {
#pragma unroll
        for (int i = 0; i < 8; i++) {
            int idx = tid + i * 256;       // 0..2047
            int s = idx >> 10, q = idx & 1023;
            int row = q >> 3, c = q & 7;
            const uint4* src = g_w2 + (tap * 2 + s) * 1024 + q;
            cp16(sb + SM_W + buf * WBUF_B + s * XT_B + row * XROW + c * 16,
                 src, 16);
        }
    };
    load_w(0, 0);
    cp_commit();

    // per-lane ldmatrix address components
    const unsigned aRowK = (unsigned)((l & 15) * XROW + ((l >> 4) & 1) * 16);
    const int bRow = (l & 7) + ((l & 16) ? 8 : 0);
    const unsigned bKoff = (l & 8) ? 16u : 0u;

    float acc[2][8][4];
#pragma unroll
    for (int tm = 0; tm < 2; tm++)
#pragma unroll
        for (int tn = 0; tn < 8; tn++)
#pragma unroll
            for (int q = 0; q < 4; q++) acc[tm][tn][q] = 0.f;

    const int SA[3] = {0, 1, 0};   // A split per pass
    const int SB[3] = {0, 0, 1};   // B split per pass

#pragma unroll 1
    for (int j = 0; j < 9; j++) {
        asm volatile("cp.async.wait_group 0;");
        __syncthreads();
        if (j < 8) { load_w(j + 1, (j + 1) & 1); cp_commit(); }

        const int kh = j / 3, kw = j % 3;
        const unsigned wbuf = sb + SM_W + (unsigned)(j & 1) * WBUF_B;

        // B row addresses per 16-pixel group (kw shift, zero row if p<0)
        unsigned bbase[4];
#pragma unroll
        for (int g = 0; g < 4; g++) {
            int p = wn * 64 + g * 16 + bRow - kw;
            bbase[g] = (p >= 0) ? (unsigned)(p * XROW + bKoff)
                                : 0xffffffffu;   // marker
        }

#pragma unroll
        for (int pass = 0; pass < 3; pass++) {
            const unsigned wbase = wbuf + (unsigned)SA[pass] * XT_B;
            const unsigned xbase = sb + SM_X + (unsigned)(kh * 2 + SB[pass]) * XT_B;
            unsigned ba[4];
#pragma unroll
            for (int g = 0; g < 4; g++)
                ba[g] = (bbase[g] != 0xffffffffu) ? (xbase + bbase[g])
                                                  : (sb + SM_ZERO + bKoff);
            const unsigned aa0 = wbase + (unsigned)(wm * 32) * XROW + aRowK;
            const unsigned aa1 = aa0 + 16 * XROW;

#pragma unroll
            for (int kc = 0; kc < 4; kc++) {
                const unsigned ko = kc * 32;   // 16 ic * 2B
                unsigned a0[4], a1[4], bf[4][4];
                ldsm4(a0, aa0 + ko);
                ldsm4(a1, aa1 + ko);
#pragma unroll
                for (int g = 0; g < 4; g++)
                    ldsm4(bf[g], (bbase[g] != 0xffffffffu) ? (ba[g] + ko)
                                                           : ba[g]);
#pragma unroll
                for (int tn = 0; tn < 8; tn++) {
                    unsigned b0 = bf[tn >> 1][(tn & 1) * 2];
                    unsigned b1 = bf[tn >> 1][(tn & 1) * 2 + 1];
                    mma16816(acc[0][tn], a0, b0, b1);
                    mma16816(acc[1][tn], a1, b0, b1);
                }
            }
        }
    }

    // ---------------- epilogue: bias + GELU + per-pixel GN ----------------
#pragma unroll
    for (int tm = 0; tm < 2; tm++) {
        const int r0 = wm * 32 + tm * 16 + (l >> 2);   // row lo; hi = +8
        const float b_lo = __ldg(bias + r0), b_hi = __ldg(bias + r0 + 8);
        const float w_lo = __ldg(gnw + r0),  w_hi = __ldg(gnw + r0 + 8);
        const float a_lo = __ldg(gnb + r0),  a_hi = __ldg(gnb + r0 + 8);

#pragma unroll
        for (int tn = 0; tn < 8; tn++) {
            float* c = acc[tm][tn];
            float glo0 = gelu_tanh(c[0] + b_lo);
            float glo1 = gelu_tanh(c[1] + b_lo);
            float ghi0 = gelu_tanh(c[2] + b_hi);
            float ghi1 = gelu_tanh(c[3] + b_hi);

            float s1a = glo0 + ghi0, s2a = glo0 * glo0 + ghi0 * ghi0;
            float s1b = glo1 + ghi1, s2b = glo1 * glo1 + ghi1 * ghi1;
#pragma unroll
            for (int m = 4; m <= 16; m <<= 1) {
                s1a += __shfl_xor_sync(0xffffffffu, s1a, m);
                s2a += __shfl_xor_sync(0xffffffffu, s2a, m);
                s1b += __shfl_xor_sync(0xffffffffu, s1b, m);
                s2b += __shfl_xor_sync(0xffffffffu, s2b, m);
            }
            float ma = s1a * (1.0f / 16.0f);
            float va = s2a * (1.0f / 16.0f) - ma * ma;
            float ra = rsqrtf(va + 1e-5f);
            float mb = s1b * (1.0f / 16.0f);
            float vb = s2b * (1.0f / 16.0f) - mb * mb;
            float rb = rsqrtf(vb + 1e-5f);

            float o_lo0 = (glo0 - ma) * ra * w_lo + a_lo;
            float o_hi0 = (ghi0 - ma) * ra * w_hi + a_hi;
            float o_lo1 = (glo1 - mb) * rb * w_lo + a_lo;
            float o_hi1 = (ghi1 - mb) * rb * w_hi + a_hi;

            int p0 = wn * 64 + tn * 8 + 2 * (l & 3);
            float* dst = out + (((size_t)n * COUT + r0) * HH + h) * WW + p0;
            *(float2*)dst = make_float2(o_lo0, o_lo1);
            *(float2*)(dst + 8 * HH * WW) = make_float2(o_hi0, o_hi1);
        }
    }
}

extern "C" void kernel_launch(void* const* d_in, const int* in_sizes, int n_in,
                              void* d_out, int out_size) {
    const float* x   = (const float*)d_in[0];
    const float* w   = (const float*)d_in[1];
    const float* b   = (const float*)d_in[2];
    const float* gnw = (const float*)d_in[3];
    const float* gnb = (const float*)d_in[4];
    float* out = (float*)d_out;

    prep_w<<<9, 256>>>(w);
    prep_x<<<dim3(HH, NB), 256>>>(x);

    cudaFuncSetAttribute(convt_hmma_kernel,
                         cudaFuncAttributeMaxDynamicSharedMemorySize, SMEM_SZ);
    convt_hmma_kernel<<<dim3(HH, NB), 256, SMEM_SZ>>>(b, gnw, gnb, out);
}

// round 9
// speedup vs baseline: 4.3375x; 2.7098x over previous
#include <cuda_runtime.h>
#include <cuda_fp16.h>
#include <math.h>
#include <stdint.h>

#define CIN   64
#define COUT  128
#define HH    128
#define WW    128
#define NB    32

// ---------------- persistent scratch (__device__ globals) -------------------
// Weights: [tap][oc(128)][ic(64)] fp16  (16KB per tap tile)
__device__ uint4 g_w1[9 * 1024];
// Activations: [n][h][pix(128)][ic(64)] fp16 (16KB per row tile)
__device__ uint4 g_x1[(size_t)NB * HH * 1024];

// ---------------- pre-pass: weights -> fp16 transposed tiles ----------------
__global__ void prep_w(const float* __restrict__ w) {
    const int tap = blockIdx.x;             // kh*3+kw
    const int kh = tap / 3, kw = tap % 3;
    __half* dst = (__half*)(g_w1 + tap * 1024);
    for (int f = threadIdx.x; f < 8192; f += 256) {   // f = oc*64 + ic
        int oc = f >> 6, ic = f & 63;
        float v = w[((size_t)(ic * COUT + oc) * 3 + kh) * 3 + kw];
        dst[f] = __float2half_rn(v);
    }
}

// ---------------- pre-pass: x -> fp16 transposed tiles ----------------------
__global__ void prep_x(const float* __restrict__ x) {
    __shared__ __half sh[128 * 72];         // padded rows (72 halves = 144B)
    const int h = blockIdx.x, n = blockIdx.y;
    const float* xb = x + (size_t)n * CIN * HH * WW;
#pragma unroll
    for (int i = 0; i < 8; i++) {
        int f = threadIdx.x + i * 256;      // 0..2047 = ic*32 + p4
        int ic = f >> 5, p4 = f & 31;
        float4 v = *(const float4*)(xb + ((size_t)ic * HH + h) * WW + p4 * 4);
        float vv[4] = {v.x, v.y, v.z, v.w};
#pragma unroll
        for (int j = 0; j < 4; j++)
            sh[(p4 * 4 + j) * 72 + ic] = __float2half_rn(vv[j]);
    }
    __syncthreads();
    uint4* dst = g_x1 + (size_t)(n * HH + h) * 1024;
    for (int q = threadIdx.x; q < 1024; q += 256) {   // q = p*8 + c (16B units)
        int p = q >> 3, c = q & 7;
        dst[q] = *(const uint4*)((const char*)sh + p * 144 + c * 16);
    }
}

// ---------------- main kernel ----------------------------------------------
// smem rows padded to 144B (9x16B) -> conflict-free ldmatrix.
#define XROW   144
#define XT_B   (128 * XROW)             // 18432 per tile
#define SM_ZERO 0                       // 256B of zeros
#define SM_X   256                      // 3 X tiles (kh = 0..2)
#define SM_W   (256 + 3 * XT_B)         // 2 W bufs (tap double buffer)
#define SMEM_SZ (SM_W + 2 * XT_B)       // 92416 -> 2 CTAs/SM

static __device__ __forceinline__ unsigned smem_u32(const void* p) {
    unsigned r;
    asm("{ .reg .u64 t; cvta.to.shared.u64 t, %1; cvt.u32.u64 %0, t; }"
        : "=r"(r) : "l"(p));
    return r;
}

__device__ __forceinline__ void cp16(unsigned dst, const void* src, int bytes) {
    asm volatile("cp.async.cg.shared.global [%0], [%1], 16, %2;"
                 :: "r"(dst), "l"(src), "r"(bytes));
}
__device__ __forceinline__ void cp_commit() {
    asm volatile("cp.async.commit_group;");
}

__device__ __forceinline__ void ldsm4(unsigned r[4], unsigned addr) {
    asm volatile("ldmatrix.sync.aligned.m8n8.x4.shared.b16 {%0,%1,%2,%3}, [%4];"
                 : "=r"(r[0]), "=r"(r[1]), "=r"(r[2]), "=r"(r[3]) : "r"(addr));
}

__device__ __forceinline__ void mma16816(float c[4], const unsigned a[4],
                                         unsigned b0, unsigned b1) {
    asm volatile(
        "mma.sync.aligned.m16n8k16.row.col.f32.f16.f16.f32 "
        "{%0,%1,%2,%3}, {%4,%5,%6,%7}, {%8,%9}, {%0,%1,%2,%3};"
        : "+f"(c[0]), "+f"(c[1]), "+f"(c[2]), "+f"(c[3])
        : "r"(a[0]), "r"(a[1]), "r"(a[2]), "r"(a[3]), "r"(b0), "r"(b1));
}

__device__ __forceinline__ float gelu_tanh(float y) {
    float u = 0.7978845608f * (y + 0.044715f * y * y * y);
    return 0.5f * y * (1.0f + tanhf(u));
}

extern __shared__ char dyn_smem[];

__global__ __launch_bounds__(256, 2)
void convt_hmma_kernel(const float* __restrict__ bias,
                       const float* __restrict__ gnw,
                       const float* __restrict__ gnb,
                       float* __restrict__ out) {
    const int h = blockIdx.x;
    const int n = blockIdx.y;
    const int tid = threadIdx.x;
    const int wid = tid >> 5;
    const int l = tid & 31;
    const int wm = wid >> 1;          // 0..3 -> oc base wm*32
    const int wn = wid & 1;           // 0..1 -> pixel base wn*64

    const unsigned sb = smem_u32(dyn_smem);

    // zero region for out-of-range B rows
    if (tid < 64) *(float*)(dyn_smem + tid * 4) = 0.f;

    // ---- prologue: 3 X tiles (kh = 0..2), zero-filled above top edge ----
#pragma unroll
    for (int i = 0; i < 12; i++) {
        int idx = tid + i * 256;           // 0..3071
        int kh = idx >> 10, q = idx & 1023;
        int gh = h - kh;
        int row = q >> 3, c = q & 7;
        const uint4* src = g_x1 + (size_t)(n * HH + (gh < 0 ? 0 : gh)) * 1024 + q;
        cp16(sb + SM_X + kh * XT_B + row * XROW + c * 16, src,
             (gh >= 0) ? 16 : 0);
    }
    cp_commit();

    auto load_w = [&](int tap, int buf) {
#pragma unroll
        for (int i = 0; i < 4; i++) {
            int q = tid + i * 256;         // 0..1023
            int row = q >> 3, c = q & 7;
            cp16(sb + SM_W + buf * XT_B + row * XROW + c * 16,
                 g_w1 + tap * 1024 + q, 16);
        }
    };
    load_w(0, 0);
    cp_commit();

    // per-lane ldmatrix address components
    const unsigned aRowK = (unsigned)((l & 15) * XROW + ((l >> 4) & 1) * 16);
    const int bRow = (l & 7) + ((l & 16) ? 8 : 0);
    const unsigned bKoff = (l & 8) ? 16u : 0u;

    float acc[2][8][4];
#pragma unroll
    for (int tm = 0; tm < 2; tm++)
#pragma unroll
        for (int tn = 0; tn < 8; tn++)
#pragma unroll
            for (int q = 0; q < 4; q++) acc[tm][tn][q] = 0.f;

#pragma unroll 1
    for (int j = 0; j < 9; j++) {
        asm volatile("cp.async.wait_group 0;");
        __syncthreads();
        if (j < 8) { load_w(j + 1, (j + 1) & 1); cp_commit(); }

        const int kh = j / 3, kw = j % 3;
        const unsigned wbase = sb + SM_W + (unsigned)(j & 1) * XT_B;
        const unsigned xbase = sb + SM_X + (unsigned)kh * XT_B;

        // B row addresses per 16-pixel group (kw shift, zero row if p<0)
        unsigned ba[4];
        bool zb[4];
#pragma unroll
        for (int g = 0; g < 4; g++) {
            int p = wn * 64 + g * 16 + bRow - kw;
            zb[g] = (p < 0);
            ba[g] = (p >= 0) ? (xbase + (unsigned)(p * XROW) + bKoff)
                             : (sb + SM_ZERO + bKoff);
        }

        const unsigned aa0 = wbase + (unsigned)(wm * 32) * XROW + aRowK;
        const unsigned aa1 = aa0 + 16 * XROW;

#pragma unroll
        for (int kc = 0; kc < 4; kc++) {
            const unsigned ko = kc * 32;   // 16 ic * 2B
            unsigned a0[4], a1[4], bf[4][4];
            ldsm4(a0, aa0 + ko);
            ldsm4(a1, aa1 + ko);
#pragma unroll
            for (int g = 0; g < 4; g++)
                ldsm4(bf[g], zb[g] ? ba[g] : (ba[g] + ko));
#pragma unroll
            for (int tn = 0; tn < 8; tn++) {
                unsigned b0 = bf[tn >> 1][(tn & 1) * 2];
                unsigned b1 = bf[tn >> 1][(tn & 1) * 2 + 1];
                mma16816(acc[0][tn], a0, b0, b1);
                mma16816(acc[1][tn], a1, b0, b1);
            }
        }
    }

    // ---------------- epilogue: bias + GELU + per-pixel GN ----------------
#pragma unroll
    for (int tm = 0; tm < 2; tm++) {
        const int r0 = wm * 32 + tm * 16 + (l >> 2);   // row lo; hi = +8
        const float b_lo = __ldg(bias + r0), b_hi = __ldg(bias + r0 + 8);
        const float w_lo = __ldg(gnw + r0),  w_hi = __ldg(gnw + r0 + 8);
        const float a_lo = __ldg(gnb + r0),  a_hi = __ldg(gnb + r0 + 8);

#pragma unroll
        for (int tn = 0; tn < 8; tn++) {
            float* c = acc[tm][tn];
            float glo0 = gelu_tanh(c[0] + b_lo);
            float glo1 = gelu_tanh(c[1] + b_lo);
            float ghi0 = gelu_tanh(c[2] + b_hi);
            float ghi1 = gelu_tanh(c[3] + b_hi);

            float s1a = glo0 + ghi0, s2a = glo0 * glo0 + ghi0 * ghi0;
            float s1b = glo1 + ghi1, s2b = glo1 * glo1 + ghi1 * ghi1;
#pragma unroll
            for (int m = 4; m <= 16; m <<= 1) {
                s1a += __shfl_xor_sync(0xffffffffu, s1a, m);
                s2a += __shfl_xor_sync(0xffffffffu, s2a, m);
                s1b += __shfl_xor_sync(0xffffffffu, s1b, m);
                s2b += __shfl_xor_sync(0xffffffffu, s2b, m);
            }
            float ma = s1a * (1.0f / 16.0f);
            float va = s2a * (1.0f / 16.0f) - ma * ma;
            float ra = rsqrtf(va + 1e-5f);
            float mb = s1b * (1.0f / 16.0f);
            float vb = s2b * (1.0f / 16.0f) - mb * mb;
            float rb = rsqrtf(vb + 1e-5f);

            float o_lo0 = (glo0 - ma) * ra * w_lo + a_lo;
            float o_hi0 = (ghi0 - ma) * ra * w_hi + a_hi;
            float o_lo1 = (glo1 - mb) * rb * w_lo + a_lo;
            float o_hi1 = (ghi1 - mb) * rb * w_hi + a_hi;

            int p0 = wn * 64 + tn * 8 + 2 * (l & 3);
            float* dst = out + (((size_t)n * COUT + r0) * HH + h) * WW + p0;
            *(float2*)dst = make_float2(o_lo0, o_lo1);
            *(float2*)(dst + 8 * HH * WW) = make_float2(o_hi0, o_hi1);
        }
    }
}

extern "C" void kernel_launch(void* const* d_in, const int* in_sizes, int n_in,
                              void* d_out, int out_size) {
    const float* x   = (const float*)d_in[0];
    const float* w   = (const float*)d_in[1];
    const float* b   = (const float*)d_in[2];
    const float* gnw = (const float*)d_in[3];
    const float* gnb = (const float*)d_in[4];
    float* out = (float*)d_out;

    prep_w<<<9, 256>>>(w);
    prep_x<<<dim3(HH, NB), 256>>>(x);

    cudaFuncSetAttribute(convt_hmma_kernel,
                         cudaFuncAttributeMaxDynamicSharedMemorySize, SMEM_SZ);
    convt_hmma_kernel<<<dim3(HH, NB), 256, SMEM_SZ>>>(b, gnw, gnb, out);
}